// round 7
// baseline (speedup 1.0000x reference)
#include <cuda_runtime.h>
#include <cstdint>

// ---------------------------------------------------------------------------
// PredNetNoMap — bf16x3 split mma.sync, interleaved hi/lo uint2 smem (LDS.64).
// 6 launches:
//  1. pred12 : buf2 = relu(gn(relu(gn(actors@W1[k]))@W2[k]) + actors)
//  2. predo  : reg  = buf2@Wo[k] + bo[k] + ctr          (MT=1: 128x64 tile)
//  3. a2     : a2   = actors @ agt_W[128:256]
//  4. distagt: feats= relu(gn(relu(gn(AGEN@dist_W1))@agt_Wtop + a2))
//  5. cls12  : cls  = (relu(gn(relu(gn(feats@cW1))@cW2)+feats)) . Wo+bo
//  6. final  : softmax(K=6) + stable desc sort + gather
// ---------------------------------------------------------------------------

namespace {
constexpr int  NACT  = 100000;
constexpr int  KM    = 6;
constexpr int  DD    = 128;
constexpr int  OUT2P = 60;
constexpr long TOT_NK = (long)NACT * KM;
constexpr long OFF_REG   = TOT_NK;
constexpr long OFF_FEATS = OFF_REG + TOT_NK * OUT2P;

// smem in uint2 units. A/V: [row][k2] stride 68 (≡4 mod 16 → conflict-free LDS.64)
// B: [k2][n] stride 132 (≡4 mod 16)
constexpr int LDA2 = 68;
constexpr int LDB2 = 132;
constexpr int U2_A   = 0;                      // 128*68 = 8704 uint2
constexpr int U2_B   = U2_A + 128 * LDA2;      // 64*132 = 8448 uint2
constexpr int U2_V   = U2_B + 64 * LDB2;       // 8704 uint2
constexpr int U2_RED = U2_V + 128 * LDA2;      // floats from here
// floats: red[128*17], red2[128*17], rstat[256] = 4608 floats = 2304 uint2
constexpr int SMEM_BYTES = (U2_RED + 2304) * 8;   // 225,280 B
}

// scratch (static device memory; no runtime allocation)
__device__ float g_buf2[TOT_NK * DD];
__device__ float g_a2[(long)NACT * DD];
__device__ float g_reg[TOT_NK * OUT2P];
__device__ float g_cls[TOT_NK];

struct KParams {
    const float* A;  long aStride;
    const float* B1; long b1Stride; int ldB1; int ncols1;
    const float* B2; long b2Stride;
    int M;
    const float* g1; const float* bt1;
    const float* g2; const float* bt2;
    float* Out;
    const float* pre;                       // EPIO3 pre-GN add (row nk/6)
    const float* biasN; const float* ctrs;  // EPIO4 / AGEN
    const float* wo; const float* wob; float* clsOut;      // EPIO5
    const float* dW0; const float* db0; const float* dReg; // AGEN
};

// ---------------- low-level helpers ----------------
__device__ __forceinline__ uint32_t pack_bf(float v_even, float v_odd) {
    uint32_t r;  // low16 = bf16(v_even), high16 = bf16(v_odd)
    asm("cvt.rn.bf16x2.f32 %0, %1, %2;" : "=r"(r) : "f"(v_odd), "f"(v_even));
    return r;
}
__device__ __forceinline__ float bf_lo_f(uint32_t p) { return __uint_as_float(p << 16); }
__device__ __forceinline__ float bf_hi_f(uint32_t p) { return __uint_as_float(p & 0xFFFF0000u); }

// split pair (v0,v1) -> uint2{ hi-pair, lo-residual-pair }
__device__ __forceinline__ uint2 split2(float v0, float v1) {
    uint32_t h = pack_bf(v0, v1);
    uint32_t l = pack_bf(v0 - bf_lo_f(h), v1 - bf_hi_f(h));
    return make_uint2(h, l);
}

__device__ __forceinline__ void mma16(float* d, uint32_t a0, uint32_t a1, uint32_t a2,
                                      uint32_t a3, uint32_t b0, uint32_t b1) {
    asm volatile("mma.sync.aligned.m16n8k16.row.col.f32.bf16.bf16.f32 "
                 "{%0,%1,%2,%3},{%4,%5,%6,%7},{%8,%9},{%0,%1,%2,%3};"
                 : "+f"(d[0]), "+f"(d[1]), "+f"(d[2]), "+f"(d[3])
                 : "r"(a0), "r"(a1), "r"(a2), "r"(a3), "r"(b0), "r"(b1));
}

// global fp32 A tile -> interleaved hi/lo uint2 smem
__device__ __forceinline__ void loadA(uint2* sA, const float* Agl,
                                      int rowBase, int M, int tid) {
#pragma unroll
    for (int t = 0; t < 8; t++) {
        int task = t * 512 + tid;          // 4096 float4 tasks
        int row = task >> 5;
        int k0  = (task & 31) * 4;
        float4 v = make_float4(0.f, 0.f, 0.f, 0.f);
        if (rowBase + row < M)
            v = *reinterpret_cast<const float4*>(Agl + (long)(rowBase + row) * DD + k0);
        uint2 p0 = split2(v.x, v.y);
        uint2 p1 = split2(v.z, v.w);
        int idx = row * LDA2 + (k0 >> 1);  // even -> 16B aligned
        *reinterpret_cast<uint4*>(sA + idx) = make_uint4(p0.x, p0.y, p1.x, p1.y);
    }
}

// global fp32 B [128 x ncols] (ld=ldB) -> interleaved hi/lo uint2 smem [k2][n]
__device__ __forceinline__ void loadB(uint2* sB, const float* Bgl,
                                      int ldB, int ncols, int tid) {
#pragma unroll
    for (int t = 0; t < 4; t++) {
        int task = t * 512 + tid;          // 2048 tasks: 64 k2 x 32 n4
        int k2 = task >> 5;
        int n0 = (task & 31) * 4;
        float4 e = make_float4(0.f, 0.f, 0.f, 0.f), o = e;
        if (n0 < ncols) {
            e = *reinterpret_cast<const float4*>(Bgl + (long)(2 * k2) * ldB + n0);
            o = *reinterpret_cast<const float4*>(Bgl + (long)(2 * k2 + 1) * ldB + n0);
        }
        uint2 p0 = split2(e.x, o.x);
        uint2 p1 = split2(e.y, o.y);
        uint2 p2 = split2(e.z, o.z);
        uint2 p3 = split2(e.w, o.w);
        int idx = k2 * LDB2 + n0;          // even -> 16B aligned
        *reinterpret_cast<uint4*>(sB + idx)     = make_uint4(p0.x, p0.y, p1.x, p1.y);
        *reinterpret_cast<uint4*>(sB + idx + 2) = make_uint4(p2.x, p2.y, p3.x, p3.y);
    }
}

// bf16x3 split layer: C[128 x 32*?] per warp tile. MT=2: 32-row warp tile; MT=1: 16.
template<int MT>
__device__ __forceinline__ void compute_layer(float acc[MT][4][4],
        const uint2* As, const uint2* Bs, int mw, int nw, int gid, int tig) {
#pragma unroll
    for (int kc = 0; kc < 8; kc++) {
        const int kb = kc * 8 + tig;
        uint32_t ah[MT][4], al[MT][4];
#pragma unroll
        for (int mt = 0; mt < MT; mt++) {
            int r = (MT == 2 ? mw * 32 + mt * 16 : mw * 16) + gid;
            uint2 p0 = As[r * LDA2 + kb];
            uint2 p1 = As[(r + 8) * LDA2 + kb];
            uint2 p2 = As[r * LDA2 + kb + 4];
            uint2 p3 = As[(r + 8) * LDA2 + kb + 4];
            ah[mt][0] = p0.x; al[mt][0] = p0.y;
            ah[mt][1] = p1.x; al[mt][1] = p1.y;
            ah[mt][2] = p2.x; al[mt][2] = p2.y;
            ah[mt][3] = p3.x; al[mt][3] = p3.y;
        }
#pragma unroll
        for (int nt = 0; nt < 4; nt++) {
            int cn = nw * 32 + nt * 8 + gid;
            uint2 pb0 = Bs[kb * LDB2 + cn];
            uint2 pb1 = Bs[(kb + 4) * LDB2 + cn];
#pragma unroll
            for (int mt = 0; mt < MT; mt++) {
                mma16(acc[mt][nt], ah[mt][0], ah[mt][1], ah[mt][2], ah[mt][3], pb0.x, pb1.x);
                mma16(acc[mt][nt], al[mt][0], al[mt][1], al[mt][2], al[mt][3], pb0.x, pb1.x);
                mma16(acc[mt][nt], ah[mt][0], ah[mt][1], ah[mt][2], ah[mt][3], pb0.y, pb1.y);
            }
        }
    }
}

// GN row statistics (MT=2 path only: 16 partial groups per row)
__device__ __forceinline__ void gn_stats2(float acc[2][4][4], float* red, float* red2,
                                          float* rstat, int mw, int nw, int gid, int tig,
                                          int tid) {
#pragma unroll
    for (int mt = 0; mt < 2; mt++)
#pragma unroll
        for (int h = 0; h < 2; h++) {
            int r = mw * 32 + mt * 16 + h * 8 + gid;
            float s = 0.f, q = 0.f;
#pragma unroll
            for (int nt = 0; nt < 4; nt++) {
                float v0 = acc[mt][nt][h * 2], v1 = acc[mt][nt][h * 2 + 1];
                s += v0 + v1;
                q += fmaf(v0, v0, v1 * v1);
            }
            red [r * 17 + nw * 4 + tig] = s;
            red2[r * 17 + nw * 4 + tig] = q;
        }
    __syncthreads();
    if (tid < 128) {
        float s = 0.f, q = 0.f;
#pragma unroll
        for (int g = 0; g < 16; g++) { s += red[tid * 17 + g]; q += red2[tid * 17 + g]; }
        float m   = s * (1.f / DD);
        float var = q * (1.f / DD) - m * m;
        rstat[tid]       = m;
        rstat[128 + tid] = rsqrtf(var + 1e-5f);
    }
    __syncthreads();
}

// EPIO: 0 plain store | 2 GN+resid(A)+relu | 3 preadd+GN+relu
//       4 bias+ctr -> reg layout (MT=1, 64 cols) | 5 GN+resid(A)+relu+dot(wo)
template<bool TWOLAYER, bool AGEN, int EPIO>
__global__ __launch_bounds__(512, 1)
void fused_k(KParams p) {
    constexpr int MT = (EPIO == 4) ? 1 : 2;
    extern __shared__ uint2 sm2[];
    uint2* As = sm2 + U2_A;
    uint2* Bs = sm2 + U2_B;
    uint2* Vs = sm2 + U2_V;
    float* red   = reinterpret_cast<float*>(sm2 + U2_RED);
    float* red2  = red + 128 * 17;
    float* rstat = red2 + 128 * 17;

    const int tid  = threadIdx.x;
    const int lane = tid & 31;
    const int w    = tid >> 5;
    const int gid  = lane >> 2, tig = lane & 3;
    const int mw   = (MT == 2) ? (w >> 2) : (w >> 1);
    const int nw   = (MT == 2) ? (w & 3)  : (w & 1);
    const int z    = blockIdx.x;
    const int rowBase = blockIdx.y * 128;

    float acc[MT][4][4];
#pragma unroll
    for (int mt = 0; mt < MT; mt++)
#pragma unroll
        for (int nt = 0; nt < 4; nt++)
#pragma unroll
            for (int j = 0; j < 4; j++) acc[mt][nt][j] = 0.f;

    // ---------------- stage A + B1 ----------------
    if (AGEN) {
        if (tid < 128) {
            int nk = rowBase + tid;
            float dx = 0.f, dy = 0.f;
            if (nk < p.M) {
                long n = nk / KM;
                dx = p.ctrs[n * 2 + 0] - p.dReg[(long)nk * OUT2P + 58];
                dy = p.ctrs[n * 2 + 1] - p.dReg[(long)nk * OUT2P + 59];
            }
            rstat[tid] = dx; rstat[128 + tid] = dy;
        }
        __syncthreads();
#pragma unroll
        for (int t = 0; t < 16; t++) {
            int pair = t * 512 + tid;      // 8192 pairs
            int r  = pair >> 6;
            int k2 = pair & 63;
            int k  = k2 * 2;
            float dx = rstat[r], dy = rstat[128 + r];
            float v0 = fmaxf(fmaf(dx, __ldg(p.dW0 + k),     fmaf(dy, __ldg(p.dW0 + DD + k),     __ldg(p.db0 + k))),     0.f);
            float v1 = fmaxf(fmaf(dx, __ldg(p.dW0 + k + 1), fmaf(dy, __ldg(p.dW0 + DD + k + 1), __ldg(p.db0 + k + 1))), 0.f);
            As[r * LDA2 + k2] = split2(v0, v1);
        }
    } else {
        loadA(As, p.A + (long)z * p.aStride, rowBase, p.M, tid);
    }
    loadB(Bs, p.B1 + (long)z * p.b1Stride, p.ldB1, p.ncols1, tid);
    __syncthreads();

    // ---------------- layer 1 ----------------
    compute_layer<MT>(acc, As, Bs, mw, nw, gid, tig);

    if (TWOLAYER) {
        gn_stats2(acc, red, red2, rstat, mw, nw, gid, tig, tid);
        // B1 dead after the syncs in gn_stats2 -> stream in B2 (overlaps GN math)
        loadB(Bs, p.B2 + (long)z * p.b2Stride, DD, DD, tid);
        const float* gg = p.g1  + (long)z * DD;
        const float* bb = p.bt1 + (long)z * DD;
#pragma unroll
        for (int mt = 0; mt < 2; mt++)
#pragma unroll
            for (int h = 0; h < 2; h++) {
                int r = mw * 32 + mt * 16 + h * 8 + gid;
                float m = rstat[r], rs = rstat[128 + r];
#pragma unroll
                for (int nt = 0; nt < 4; nt++) {
                    int col = nw * 32 + nt * 8 + tig * 2;
                    float v0 = fmaxf((acc[mt][nt][h * 2]     - m) * rs * __ldg(gg + col)     + __ldg(bb + col),     0.f);
                    float v1 = fmaxf((acc[mt][nt][h * 2 + 1] - m) * rs * __ldg(gg + col + 1) + __ldg(bb + col + 1), 0.f);
                    Vs[r * LDA2 + (col >> 1)] = split2(v0, v1);
                    acc[mt][nt][h * 2] = 0.f; acc[mt][nt][h * 2 + 1] = 0.f;
                }
            }
        __syncthreads();
        // ---------------- layer 2 ----------------
        compute_layer<MT>(acc, Vs, Bs, mw, nw, gid, tig);
    }

    // ---------------- out epilogue ----------------
    if (EPIO == 0) {
#pragma unroll
        for (int mt = 0; mt < 2; mt++)
#pragma unroll
            for (int h = 0; h < 2; h++) {
                int r = mw * 32 + mt * 16 + h * 8 + gid;
                int n = rowBase + r;
                if (n < p.M) {
#pragma unroll
                    for (int nt = 0; nt < 4; nt++) {
                        int col = nw * 32 + nt * 8 + tig * 2;
                        *reinterpret_cast<float2*>(p.Out + ((long)z * p.M + n) * DD + col) =
                            make_float2(acc[mt][nt][h * 2], acc[mt][nt][h * 2 + 1]);
                    }
                }
            }
        return;
    }
    if (EPIO == 4) {   // MT=1: rows mw*16.., cols nw*32.. (<=64, ncols=60)
#pragma unroll
        for (int h = 0; h < 2; h++) {
            int r = mw * 16 + h * 8 + gid;
            int n = rowBase + r;
            if (n < p.M) {
                float2 cc = *reinterpret_cast<const float2*>(p.ctrs + (long)n * 2);
#pragma unroll
                for (int nt = 0; nt < 4; nt++) {
                    int col = nw * 32 + nt * 8 + tig * 2;
                    if (col < OUT2P) {
                        float v0 = acc[0][nt][h * 2]     + __ldg(p.biasN + z * OUT2P + col)     + cc.x;
                        float v1 = acc[0][nt][h * 2 + 1] + __ldg(p.biasN + z * OUT2P + col + 1) + cc.y;
                        *reinterpret_cast<float2*>(p.Out + ((long)n * KM + z) * OUT2P + col) =
                            make_float2(v0, v1);
                    }
                }
            }
        }
        return;
    }

    if (EPIO == 3) {   // pre-GN add of a2[n/6]
#pragma unroll
        for (int mt = 0; mt < 2; mt++)
#pragma unroll
            for (int h = 0; h < 2; h++) {
                int r = mw * 32 + mt * 16 + h * 8 + gid;
                int n = rowBase + r;
                if (n < p.M) {
                    const float* pa = p.pre + (long)(n / KM) * DD;
#pragma unroll
                    for (int nt = 0; nt < 4; nt++) {
                        int col = nw * 32 + nt * 8 + tig * 2;
                        float2 pv = *reinterpret_cast<const float2*>(pa + col);
                        acc[mt][nt][h * 2]     += pv.x;
                        acc[mt][nt][h * 2 + 1] += pv.y;
                    }
                }
            }
    }
    gn_stats2(acc, red, red2, rstat, mw, nw, gid, tig, tid);
    {
        const float* gg = p.g2  + (long)z * DD;
        const float* bb = p.bt2 + (long)z * DD;
#pragma unroll
        for (int mt = 0; mt < 2; mt++)
#pragma unroll
            for (int h = 0; h < 2; h++) {
                int r = mw * 32 + mt * 16 + h * 8 + gid;
                int n = rowBase + r;
                float m = rstat[r], rs = rstat[128 + r];
                float ds = 0.f;
#pragma unroll
                for (int nt = 0; nt < 4; nt++) {
                    int col = nw * 32 + nt * 8 + tig * 2;
                    float v0 = (acc[mt][nt][h * 2]     - m) * rs * __ldg(gg + col)     + __ldg(bb + col);
                    float v1 = (acc[mt][nt][h * 2 + 1] - m) * rs * __ldg(gg + col + 1) + __ldg(bb + col + 1);
                    if (EPIO == 2 || EPIO == 5) {   // residual = original A tile (hi+lo)
                        uint2 q = As[r * LDA2 + (col >> 1)];
                        v0 += bf_lo_f(q.x) + bf_lo_f(q.y);
                        v1 += bf_hi_f(q.x) + bf_hi_f(q.y);
                    }
                    v0 = fmaxf(v0, 0.f); v1 = fmaxf(v1, 0.f);
                    if (EPIO == 5) {
                        ds += v0 * __ldg(p.wo + col) + v1 * __ldg(p.wo + col + 1);
                    } else if (n < p.M) {
                        *reinterpret_cast<float2*>(p.Out + ((long)z * p.M + n) * DD + col) =
                            make_float2(v0, v1);
                    }
                }
                if (EPIO == 5) red[r * 17 + nw * 4 + tig] = ds;
            }
    }
    if (EPIO == 5) {
        __syncthreads();
        if (tid < 128) {
            float s = 0.f;
#pragma unroll
            for (int g = 0; g < 16; g++) s += red[tid * 17 + g];
            int n = rowBase + tid;
            if (n < p.M) p.clsOut[n] = s + __ldg(p.wob);
        }
    }
}

// softmax over K=6, stable descending sort, reorder cls + reg into d_out
__global__ void final_k(const float* __restrict__ clsRaw, const float* __restrict__ reg,
                        float* __restrict__ out) {
    long gw = ((long)blockIdx.x * blockDim.x + threadIdx.x) >> 5;
    int lane = threadIdx.x & 31;
    if (gw >= NACT) return;
    long n = gw;
    float v[KM];
#pragma unroll
    for (int k = 0; k < KM; k++) v[k] = clsRaw[n * KM + k];
    float mx = v[0];
#pragma unroll
    for (int k = 1; k < KM; k++) mx = fmaxf(mx, v[k]);
    float e[KM]; float s = 0.f;
#pragma unroll
    for (int k = 0; k < KM; k++) { e[k] = expf(v[k] - mx); s += e[k]; }
    float inv = 1.f / s;
    int order[KM]; bool used[KM];
#pragma unroll
    for (int k = 0; k < KM; k++) used[k] = false;
#pragma unroll
    for (int j = 0; j < KM; j++) {   // stable selection: strict >, first index wins
        int best = 0; float bv = -1e30f;
#pragma unroll
        for (int k = 0; k < KM; k++)
            if (!used[k] && v[k] > bv) { bv = v[k]; best = k; }
        used[best] = true;
        order[j] = best;
    }
    if (lane < KM) out[n * KM + lane] = e[order[lane]] * inv;
    const float* src0 = reg + n * KM * OUT2P;
    float* dst0 = out + OFF_REG + n * KM * OUT2P;
#pragma unroll
    for (int j = 0; j < KM; j++) {
        const float* src = src0 + order[j] * OUT2P;
        float* dst = dst0 + (long)j * OUT2P;
        for (int t = lane; t < OUT2P; t += 32) dst[t] = src[t];
    }
}

extern "C" void kernel_launch(void* const* d_in, const int* in_sizes, int n_in,
                              void* d_out, int out_size) {
    const float* actors  = (const float*)d_in[0];
    const float* ctrs    = (const float*)d_in[1];
    const float* pred_W1 = (const float*)d_in[2];
    const float* pred_g1 = (const float*)d_in[3];
    const float* pred_b1 = (const float*)d_in[4];
    const float* pred_W2 = (const float*)d_in[5];
    const float* pred_g2 = (const float*)d_in[6];
    const float* pred_b2 = (const float*)d_in[7];
    const float* pred_Wo = (const float*)d_in[8];
    const float* pred_bo = (const float*)d_in[9];
    const float* dist_W0 = (const float*)d_in[10];
    const float* dist_b0 = (const float*)d_in[11];
    const float* dist_W1 = (const float*)d_in[12];
    const float* dist_g1 = (const float*)d_in[13];
    const float* dist_b1 = (const float*)d_in[14];
    const float* agt_W   = (const float*)d_in[15];
    const float* agt_g   = (const float*)d_in[16];
    const float* agt_b   = (const float*)d_in[17];
    const float* cls_W1  = (const float*)d_in[18];
    const float* cls_g1  = (const float*)d_in[19];
    const float* cls_b1  = (const float*)d_in[20];
    const float* cls_W2  = (const float*)d_in[21];
    const float* cls_g2  = (const float*)d_in[22];
    const float* cls_b2  = (const float*)d_in[23];
    const float* cls_Wo  = (const float*)d_in[24];
    const float* cls_bo  = (const float*)d_in[25];
    float* out = (float*)d_out;

    float *buf2, *a2, *reg, *clsraw;
    cudaGetSymbolAddress((void**)&buf2,   g_buf2);
    cudaGetSymbolAddress((void**)&a2,     g_a2);
    cudaGetSymbolAddress((void**)&reg,    g_reg);
    cudaGetSymbolAddress((void**)&clsraw, g_cls);
    float* feats = out + OFF_FEATS;

    cudaFuncSetAttribute(fused_k<true,  false, 2>, cudaFuncAttributeMaxDynamicSharedMemorySize, SMEM_BYTES);
    cudaFuncSetAttribute(fused_k<false, false, 4>, cudaFuncAttributeMaxDynamicSharedMemorySize, SMEM_BYTES);
    cudaFuncSetAttribute(fused_k<false, false, 0>, cudaFuncAttributeMaxDynamicSharedMemorySize, SMEM_BYTES);
    cudaFuncSetAttribute(fused_k<true,  true,  3>, cudaFuncAttributeMaxDynamicSharedMemorySize, SMEM_BYTES);
    cudaFuncSetAttribute(fused_k<true,  false, 5>, cudaFuncAttributeMaxDynamicSharedMemorySize, SMEM_BYTES);

    const int gy_N  = (NACT + 127) / 128;          // 782
    const int gy_NK = ((int)TOT_NK + 127) / 128;   // 4688

    KParams p;

    // 1. pred12 (two-layer, resid = actors from smem A)
    p = {}; p.A = actors; p.aStride = 0;
    p.B1 = pred_W1; p.b1Stride = (long)DD * DD; p.ldB1 = DD; p.ncols1 = DD;
    p.B2 = pred_W2; p.b2Stride = (long)DD * DD;
    p.M = NACT; p.g1 = pred_g1; p.bt1 = pred_b1; p.g2 = pred_g2; p.bt2 = pred_b2;
    p.Out = buf2;
    fused_k<true, false, 2><<<dim3(KM, gy_N), 512, SMEM_BYTES>>>(p);

    // 2. predo (single layer, MT=1 128x64 tile, bias + ctr, reg layout)
    p = {}; p.A = buf2; p.aStride = (long)NACT * DD;
    p.B1 = pred_Wo; p.b1Stride = (long)DD * OUT2P; p.ldB1 = OUT2P; p.ncols1 = OUT2P;
    p.M = NACT; p.Out = reg; p.biasN = pred_bo; p.ctrs = ctrs;
    fused_k<false, false, 4><<<dim3(KM, gy_N), 512, SMEM_BYTES>>>(p);

    // 3. a2 = actors @ agt_W[128:256]
    p = {}; p.A = actors; p.aStride = 0;
    p.B1 = agt_W + DD * DD; p.b1Stride = 0; p.ldB1 = DD; p.ncols1 = DD;
    p.M = NACT; p.Out = a2;
    fused_k<false, false, 0><<<dim3(1, gy_N), 512, SMEM_BYTES>>>(p);

    // 4. distagt (A generated; two-layer; pre-add a2; out -> feats)
    p = {}; p.A = nullptr; p.aStride = 0;
    p.B1 = dist_W1; p.b1Stride = 0; p.ldB1 = DD; p.ncols1 = DD;
    p.B2 = agt_W;  p.b2Stride = 0;
    p.M = (int)TOT_NK; p.g1 = dist_g1; p.bt1 = dist_b1; p.g2 = agt_g; p.bt2 = agt_b;
    p.Out = feats; p.pre = a2;
    p.ctrs = ctrs; p.dW0 = dist_W0; p.db0 = dist_b0; p.dReg = reg;
    fused_k<true, true, 3><<<dim3(1, gy_NK), 512, SMEM_BYTES>>>(p);

    // 5. cls12 (two-layer, resid = feats from smem A, fused Wo dot)
    p = {}; p.A = feats; p.aStride = 0;
    p.B1 = cls_W1; p.b1Stride = 0; p.ldB1 = DD; p.ncols1 = DD;
    p.B2 = cls_W2; p.b2Stride = 0;
    p.M = (int)TOT_NK; p.g1 = cls_g1; p.bt1 = cls_b1; p.g2 = cls_g2; p.bt2 = cls_b2;
    p.wo = cls_Wo; p.wob = cls_bo; p.clsOut = clsraw;
    fused_k<true, false, 5><<<dim3(1, gy_NK), 512, SMEM_BYTES>>>(p);

    // 6. softmax + stable sort + gather
    {
        long threads = (long)NACT * 32;
        final_k<<<(int)((threads + 255) / 256), 256>>>(clsraw, reg, out);
    }
}

// round 11
// speedup vs baseline: 1.0002x; 1.0002x over previous
#include <cuda_runtime.h>
#include <cstdint>

// ---------------------------------------------------------------------------
// PredNetNoMap — bf16x3 split mma.sync, interleaved hi/lo uint2 smem (LDS.64).
// 6 launches:
//  1. pred12 : buf2 = relu(gn(relu(gn(actors@W1[k]))@W2[k]) + actors)
//  2. predo  : reg  = buf2@Wo[k] + bo[k] + ctr          (MT=1: 128x64 tile)
//  3. a2     : a2   = actors @ agt_W[128:256]
//  4. distagt: feats= relu(gn(relu(gn(AGEN@dist_W1))@agt_Wtop + a2))
//  5. cls12  : cls  = (relu(gn(relu(gn(feats@cW1))@cW2)+feats)) . Wo+bo
//  6. final  : softmax(K=6) + stable desc sort + gather
// ---------------------------------------------------------------------------

namespace {
constexpr int  NACT  = 100000;
constexpr int  KM    = 6;
constexpr int  DD    = 128;
constexpr int  OUT2P = 60;
constexpr long TOT_NK = (long)NACT * KM;
constexpr long OFF_REG   = TOT_NK;
constexpr long OFF_FEATS = OFF_REG + TOT_NK * OUT2P;

// smem in uint2 units. A/V: [row][k2] stride 68 (≡4 mod 16 → conflict-free LDS.64)
// B: [k2][n] stride 132 (≡4 mod 16)
constexpr int LDA2 = 68;
constexpr int LDB2 = 132;
constexpr int U2_A   = 0;                      // 128*68 = 8704 uint2
constexpr int U2_B   = U2_A + 128 * LDA2;      // 64*132 = 8448 uint2
constexpr int U2_V   = U2_B + 64 * LDB2;       // 8704 uint2
constexpr int U2_RED = U2_V + 128 * LDA2;      // floats from here
// floats: red[128*17], red2[128*17], rstat[256] = 4608 floats = 2304 uint2
constexpr int SMEM_BYTES = (U2_RED + 2304) * 8;   // 225,280 B
}

// scratch (static device memory; no runtime allocation)
__device__ float g_buf2[TOT_NK * DD];
__device__ float g_a2[(long)NACT * DD];
__device__ float g_reg[TOT_NK * OUT2P];
__device__ float g_cls[TOT_NK];

struct KParams {
    const float* A;  long aStride;
    const float* B1; long b1Stride; int ldB1; int ncols1;
    const float* B2; long b2Stride;
    int M;
    const float* g1; const float* bt1;
    const float* g2; const float* bt2;
    float* Out;
    const float* pre;                       // EPIO3 pre-GN add (row nk/6)
    const float* biasN; const float* ctrs;  // EPIO4 / AGEN
    const float* wo; const float* wob; float* clsOut;      // EPIO5
    const float* dW0; const float* db0; const float* dReg; // AGEN
};

// ---------------- low-level helpers ----------------
__device__ __forceinline__ uint32_t pack_bf(float v_even, float v_odd) {
    uint32_t r;  // low16 = bf16(v_even), high16 = bf16(v_odd)
    asm("cvt.rn.bf16x2.f32 %0, %1, %2;" : "=r"(r) : "f"(v_odd), "f"(v_even));
    return r;
}
__device__ __forceinline__ float bf_lo_f(uint32_t p) { return __uint_as_float(p << 16); }
__device__ __forceinline__ float bf_hi_f(uint32_t p) { return __uint_as_float(p & 0xFFFF0000u); }

// split pair (v0,v1) -> uint2{ hi-pair, lo-residual-pair }
__device__ __forceinline__ uint2 split2(float v0, float v1) {
    uint32_t h = pack_bf(v0, v1);
    uint32_t l = pack_bf(v0 - bf_lo_f(h), v1 - bf_hi_f(h));
    return make_uint2(h, l);
}

__device__ __forceinline__ void mma16(float* d, uint32_t a0, uint32_t a1, uint32_t a2,
                                      uint32_t a3, uint32_t b0, uint32_t b1) {
    asm volatile("mma.sync.aligned.m16n8k16.row.col.f32.bf16.bf16.f32 "
                 "{%0,%1,%2,%3},{%4,%5,%6,%7},{%8,%9},{%0,%1,%2,%3};"
                 : "+f"(d[0]), "+f"(d[1]), "+f"(d[2]), "+f"(d[3])
                 : "r"(a0), "r"(a1), "r"(a2), "r"(a3), "r"(b0), "r"(b1));
}

// global fp32 A tile -> interleaved hi/lo uint2 smem
__device__ __forceinline__ void loadA(uint2* sA, const float* Agl,
                                      int rowBase, int M, int tid) {
#pragma unroll
    for (int t = 0; t < 8; t++) {
        int task = t * 512 + tid;          // 4096 float4 tasks
        int row = task >> 5;
        int k0  = (task & 31) * 4;
        float4 v = make_float4(0.f, 0.f, 0.f, 0.f);
        if (rowBase + row < M)
            v = *reinterpret_cast<const float4*>(Agl + (long)(rowBase + row) * DD + k0);
        uint2 p0 = split2(v.x, v.y);
        uint2 p1 = split2(v.z, v.w);
        int idx = row * LDA2 + (k0 >> 1);  // even -> 16B aligned
        *reinterpret_cast<uint4*>(sA + idx) = make_uint4(p0.x, p0.y, p1.x, p1.y);
    }
}

// global fp32 B [128 x ncols] (ld=ldB) -> interleaved hi/lo uint2 smem [k2][n]
__device__ __forceinline__ void loadB(uint2* sB, const float* Bgl,
                                      int ldB, int ncols, int tid) {
#pragma unroll
    for (int t = 0; t < 4; t++) {
        int task = t * 512 + tid;          // 2048 tasks: 64 k2 x 32 n4
        int k2 = task >> 5;
        int n0 = (task & 31) * 4;
        float4 e = make_float4(0.f, 0.f, 0.f, 0.f), o = e;
        if (n0 < ncols) {
            e = *reinterpret_cast<const float4*>(Bgl + (long)(2 * k2) * ldB + n0);
            o = *reinterpret_cast<const float4*>(Bgl + (long)(2 * k2 + 1) * ldB + n0);
        }
        uint2 p0 = split2(e.x, o.x);
        uint2 p1 = split2(e.y, o.y);
        uint2 p2 = split2(e.z, o.z);
        uint2 p3 = split2(e.w, o.w);
        int idx = k2 * LDB2 + n0;          // even -> 16B aligned
        *reinterpret_cast<uint4*>(sB + idx)     = make_uint4(p0.x, p0.y, p1.x, p1.y);
        *reinterpret_cast<uint4*>(sB + idx + 2) = make_uint4(p2.x, p2.y, p3.x, p3.y);
    }
}

// bf16x3 split layer: C[128 x 32*?] per warp tile. MT=2: 32-row warp tile; MT=1: 16.
template<int MT>
__device__ __forceinline__ void compute_layer(float acc[MT][4][4],
        const uint2* As, const uint2* Bs, int mw, int nw, int gid, int tig) {
#pragma unroll
    for (int kc = 0; kc < 8; kc++) {
        const int kb = kc * 8 + tig;
        uint32_t ah[MT][4], al[MT][4];
#pragma unroll
        for (int mt = 0; mt < MT; mt++) {
            int r = (MT == 2 ? mw * 32 + mt * 16 : mw * 16) + gid;
            uint2 p0 = As[r * LDA2 + kb];
            uint2 p1 = As[(r + 8) * LDA2 + kb];
            uint2 p2 = As[r * LDA2 + kb + 4];
            uint2 p3 = As[(r + 8) * LDA2 + kb + 4];
            ah[mt][0] = p0.x; al[mt][0] = p0.y;
            ah[mt][1] = p1.x; al[mt][1] = p1.y;
            ah[mt][2] = p2.x; al[mt][2] = p2.y;
            ah[mt][3] = p3.x; al[mt][3] = p3.y;
        }
#pragma unroll
        for (int nt = 0; nt < 4; nt++) {
            int cn = nw * 32 + nt * 8 + gid;
            uint2 pb0 = Bs[kb * LDB2 + cn];
            uint2 pb1 = Bs[(kb + 4) * LDB2 + cn];
#pragma unroll
            for (int mt = 0; mt < MT; mt++) {
                mma16(acc[mt][nt], ah[mt][0], ah[mt][1], ah[mt][2], ah[mt][3], pb0.x, pb1.x);
                mma16(acc[mt][nt], al[mt][0], al[mt][1], al[mt][2], al[mt][3], pb0.x, pb1.x);
                mma16(acc[mt][nt], ah[mt][0], ah[mt][1], ah[mt][2], ah[mt][3], pb0.y, pb1.y);
            }
        }
    }
}

// GN row statistics (MT=2 path only: 16 partial groups per row)
__device__ __forceinline__ void gn_stats2(float acc[2][4][4], float* red, float* red2,
                                          float* rstat, int mw, int nw, int gid, int tig,
                                          int tid) {
#pragma unroll
    for (int mt = 0; mt < 2; mt++)
#pragma unroll
        for (int h = 0; h < 2; h++) {
            int r = mw * 32 + mt * 16 + h * 8 + gid;
            float s = 0.f, q = 0.f;
#pragma unroll
            for (int nt = 0; nt < 4; nt++) {
                float v0 = acc[mt][nt][h * 2], v1 = acc[mt][nt][h * 2 + 1];
                s += v0 + v1;
                q += fmaf(v0, v0, v1 * v1);
            }
            red [r * 17 + nw * 4 + tig] = s;
            red2[r * 17 + nw * 4 + tig] = q;
        }
    __syncthreads();
    if (tid < 128) {
        float s = 0.f, q = 0.f;
#pragma unroll
        for (int g = 0; g < 16; g++) { s += red[tid * 17 + g]; q += red2[tid * 17 + g]; }
        float m   = s * (1.f / DD);
        float var = q * (1.f / DD) - m * m;
        rstat[tid]       = m;
        rstat[128 + tid] = rsqrtf(var + 1e-5f);
    }
    __syncthreads();
}

// EPIO: 0 plain store | 2 GN+resid(A)+relu | 3 preadd+GN+relu
//       4 bias+ctr -> reg layout (MT=1, 64 cols) | 5 GN+resid(A)+relu+dot(wo)
template<bool TWOLAYER, bool AGEN, int EPIO>
__global__ __launch_bounds__(512, 1)
void fused_k(KParams p) {
    constexpr int MT = (EPIO == 4) ? 1 : 2;
    extern __shared__ uint2 sm2[];
    uint2* As = sm2 + U2_A;
    uint2* Bs = sm2 + U2_B;
    uint2* Vs = sm2 + U2_V;
    float* red   = reinterpret_cast<float*>(sm2 + U2_RED);
    float* red2  = red + 128 * 17;
    float* rstat = red2 + 128 * 17;

    const int tid  = threadIdx.x;
    const int lane = tid & 31;
    const int w    = tid >> 5;
    const int gid  = lane >> 2, tig = lane & 3;
    const int mw   = (MT == 2) ? (w >> 2) : (w >> 1);
    const int nw   = (MT == 2) ? (w & 3)  : (w & 1);
    const int z    = blockIdx.x;
    const int rowBase = blockIdx.y * 128;

    float acc[MT][4][4];
#pragma unroll
    for (int mt = 0; mt < MT; mt++)
#pragma unroll
        for (int nt = 0; nt < 4; nt++)
#pragma unroll
            for (int j = 0; j < 4; j++) acc[mt][nt][j] = 0.f;

    // ---------------- stage A + B1 ----------------
    if (AGEN) {
        if (tid < 128) {
            int nk = rowBase + tid;
            float dx = 0.f, dy = 0.f;
            if (nk < p.M) {
                long n = nk / KM;
                dx = p.ctrs[n * 2 + 0] - p.dReg[(long)nk * OUT2P + 58];
                dy = p.ctrs[n * 2 + 1] - p.dReg[(long)nk * OUT2P + 59];
            }
            rstat[tid] = dx; rstat[128 + tid] = dy;
        }
        __syncthreads();
#pragma unroll
        for (int t = 0; t < 16; t++) {
            int pair = t * 512 + tid;      // 8192 pairs
            int r  = pair >> 6;
            int k2 = pair & 63;
            int k  = k2 * 2;
            float dx = rstat[r], dy = rstat[128 + r];
            float v0 = fmaxf(fmaf(dx, __ldg(p.dW0 + k),     fmaf(dy, __ldg(p.dW0 + DD + k),     __ldg(p.db0 + k))),     0.f);
            float v1 = fmaxf(fmaf(dx, __ldg(p.dW0 + k + 1), fmaf(dy, __ldg(p.dW0 + DD + k + 1), __ldg(p.db0 + k + 1))), 0.f);
            As[r * LDA2 + k2] = split2(v0, v1);
        }
    } else {
        loadA(As, p.A + (long)z * p.aStride, rowBase, p.M, tid);
    }
    loadB(Bs, p.B1 + (long)z * p.b1Stride, p.ldB1, p.ncols1, tid);
    __syncthreads();

    // ---------------- layer 1 ----------------
    compute_layer<MT>(acc, As, Bs, mw, nw, gid, tig);

    if (TWOLAYER) {
        gn_stats2(acc, red, red2, rstat, mw, nw, gid, tig, tid);
        // B1 dead after the syncs in gn_stats2 -> stream in B2 (overlaps GN math)
        loadB(Bs, p.B2 + (long)z * p.b2Stride, DD, DD, tid);
        const float* gg = p.g1  + (long)z * DD;
        const float* bb = p.bt1 + (long)z * DD;
#pragma unroll
        for (int mt = 0; mt < 2; mt++)
#pragma unroll
            for (int h = 0; h < 2; h++) {
                int r = mw * 32 + mt * 16 + h * 8 + gid;
                float m = rstat[r], rs = rstat[128 + r];
#pragma unroll
                for (int nt = 0; nt < 4; nt++) {
                    int col = nw * 32 + nt * 8 + tig * 2;
                    float v0 = fmaxf((acc[mt][nt][h * 2]     - m) * rs * __ldg(gg + col)     + __ldg(bb + col),     0.f);
                    float v1 = fmaxf((acc[mt][nt][h * 2 + 1] - m) * rs * __ldg(gg + col + 1) + __ldg(bb + col + 1), 0.f);
                    Vs[r * LDA2 + (col >> 1)] = split2(v0, v1);
                    acc[mt][nt][h * 2] = 0.f; acc[mt][nt][h * 2 + 1] = 0.f;
                }
            }
        __syncthreads();
        // ---------------- layer 2 ----------------
        compute_layer<MT>(acc, Vs, Bs, mw, nw, gid, tig);
    }

    // ---------------- out epilogue ----------------
    if (EPIO == 0) {
#pragma unroll
        for (int mt = 0; mt < 2; mt++)
#pragma unroll
            for (int h = 0; h < 2; h++) {
                int r = mw * 32 + mt * 16 + h * 8 + gid;
                int n = rowBase + r;
                if (n < p.M) {
#pragma unroll
                    for (int nt = 0; nt < 4; nt++) {
                        int col = nw * 32 + nt * 8 + tig * 2;
                        *reinterpret_cast<float2*>(p.Out + ((long)z * p.M + n) * DD + col) =
                            make_float2(acc[mt][nt][h * 2], acc[mt][nt][h * 2 + 1]);
                    }
                }
            }
        return;
    }
    if (EPIO == 4) {   // MT=1: rows mw*16.., cols nw*32.. (<=64, ncols=60)
#pragma unroll
        for (int h = 0; h < 2; h++) {
            int r = mw * 16 + h * 8 + gid;
            int n = rowBase + r;
            if (n < p.M) {
                float2 cc = *reinterpret_cast<const float2*>(p.ctrs + (long)n * 2);
#pragma unroll
                for (int nt = 0; nt < 4; nt++) {
                    int col = nw * 32 + nt * 8 + tig * 2;
                    if (col < OUT2P) {
                        float v0 = acc[0][nt][h * 2]     + __ldg(p.biasN + z * OUT2P + col)     + cc.x;
                        float v1 = acc[0][nt][h * 2 + 1] + __ldg(p.biasN + z * OUT2P + col + 1) + cc.y;
                        *reinterpret_cast<float2*>(p.Out + ((long)n * KM + z) * OUT2P + col) =
                            make_float2(v0, v1);
                    }
                }
            }
        }
        return;
    }

    if (EPIO == 3) {   // pre-GN add of a2[n/6]
#pragma unroll
        for (int mt = 0; mt < 2; mt++)
#pragma unroll
            for (int h = 0; h < 2; h++) {
                int r = mw * 32 + mt * 16 + h * 8 + gid;
                int n = rowBase + r;
                if (n < p.M) {
                    const float* pa = p.pre + (long)(n / KM) * DD;
#pragma unroll
                    for (int nt = 0; nt < 4; nt++) {
                        int col = nw * 32 + nt * 8 + tig * 2;
                        float2 pv = *reinterpret_cast<const float2*>(pa + col);
                        acc[mt][nt][h * 2]     += pv.x;
                        acc[mt][nt][h * 2 + 1] += pv.y;
                    }
                }
            }
    }
    gn_stats2(acc, red, red2, rstat, mw, nw, gid, tig, tid);
    {
        const float* gg = p.g2  + (long)z * DD;
        const float* bb = p.bt2 + (long)z * DD;
#pragma unroll
        for (int mt = 0; mt < 2; mt++)
#pragma unroll
            for (int h = 0; h < 2; h++) {
                int r = mw * 32 + mt * 16 + h * 8 + gid;
                int n = rowBase + r;
                float m = rstat[r], rs = rstat[128 + r];
                float ds = 0.f;
#pragma unroll
                for (int nt = 0; nt < 4; nt++) {
                    int col = nw * 32 + nt * 8 + tig * 2;
                    float v0 = (acc[mt][nt][h * 2]     - m) * rs * __ldg(gg + col)     + __ldg(bb + col);
                    float v1 = (acc[mt][nt][h * 2 + 1] - m) * rs * __ldg(gg + col + 1) + __ldg(bb + col + 1);
                    if (EPIO == 2 || EPIO == 5) {   // residual = original A tile (hi+lo)
                        uint2 q = As[r * LDA2 + (col >> 1)];
                        v0 += bf_lo_f(q.x) + bf_lo_f(q.y);
                        v1 += bf_hi_f(q.x) + bf_hi_f(q.y);
                    }
                    v0 = fmaxf(v0, 0.f); v1 = fmaxf(v1, 0.f);
                    if (EPIO == 5) {
                        ds += v0 * __ldg(p.wo + col) + v1 * __ldg(p.wo + col + 1);
                    } else if (n < p.M) {
                        *reinterpret_cast<float2*>(p.Out + ((long)z * p.M + n) * DD + col) =
                            make_float2(v0, v1);
                    }
                }
                if (EPIO == 5) red[r * 17 + nw * 4 + tig] = ds;
            }
    }
    if (EPIO == 5) {
        __syncthreads();
        if (tid < 128) {
            float s = 0.f;
#pragma unroll
            for (int g = 0; g < 16; g++) s += red[tid * 17 + g];
            int n = rowBase + tid;
            if (n < p.M) p.clsOut[n] = s + __ldg(p.wob);
        }
    }
}

// softmax over K=6, stable descending sort, reorder cls + reg into d_out
__global__ void final_k(const float* __restrict__ clsRaw, const float* __restrict__ reg,
                        float* __restrict__ out) {
    long gw = ((long)blockIdx.x * blockDim.x + threadIdx.x) >> 5;
    int lane = threadIdx.x & 31;
    if (gw >= NACT) return;
    long n = gw;
    float v[KM];
#pragma unroll
    for (int k = 0; k < KM; k++) v[k] = clsRaw[n * KM + k];
    float mx = v[0];
#pragma unroll
    for (int k = 1; k < KM; k++) mx = fmaxf(mx, v[k]);
    float e[KM]; float s = 0.f;
#pragma unroll
    for (int k = 0; k < KM; k++) { e[k] = expf(v[k] - mx); s += e[k]; }
    float inv = 1.f / s;
    int order[KM]; bool used[KM];
#pragma unroll
    for (int k = 0; k < KM; k++) used[k] = false;
#pragma unroll
    for (int j = 0; j < KM; j++) {   // stable selection: strict >, first index wins
        int best = 0; float bv = -1e30f;
#pragma unroll
        for (int k = 0; k < KM; k++)
            if (!used[k] && v[k] > bv) { bv = v[k]; best = k; }
        used[best] = true;
        order[j] = best;
    }
    if (lane < KM) out[n * KM + lane] = e[order[lane]] * inv;
    const float* src0 = reg + n * KM * OUT2P;
    float* dst0 = out + OFF_REG + n * KM * OUT2P;
#pragma unroll
    for (int j = 0; j < KM; j++) {
        const float* src = src0 + order[j] * OUT2P;
        float* dst = dst0 + (long)j * OUT2P;
        for (int t = lane; t < OUT2P; t += 32) dst[t] = src[t];
    }
}

extern "C" void kernel_launch(void* const* d_in, const int* in_sizes, int n_in,
                              void* d_out, int out_size) {
    const float* actors  = (const float*)d_in[0];
    const float* ctrs    = (const float*)d_in[1];
    const float* pred_W1 = (const float*)d_in[2];
    const float* pred_g1 = (const float*)d_in[3];
    const float* pred_b1 = (const float*)d_in[4];
    const float* pred_W2 = (const float*)d_in[5];
    const float* pred_g2 = (const float*)d_in[6];
    const float* pred_b2 = (const float*)d_in[7];
    const float* pred_Wo = (const float*)d_in[8];
    const float* pred_bo = (const float*)d_in[9];
    const float* dist_W0 = (const float*)d_in[10];
    const float* dist_b0 = (const float*)d_in[11];
    const float* dist_W1 = (const float*)d_in[12];
    const float* dist_g1 = (const float*)d_in[13];
    const float* dist_b1 = (const float*)d_in[14];
    const float* agt_W   = (const float*)d_in[15];
    const float* agt_g   = (const float*)d_in[16];
    const float* agt_b   = (const float*)d_in[17];
    const float* cls_W1  = (const float*)d_in[18];
    const float* cls_g1  = (const float*)d_in[19];
    const float* cls_b1  = (const float*)d_in[20];
    const float* cls_W2  = (const float*)d_in[21];
    const float* cls_g2  = (const float*)d_in[22];
    const float* cls_b2  = (const float*)d_in[23];
    const float* cls_Wo  = (const float*)d_in[24];
    const float* cls_bo  = (const float*)d_in[25];
    float* out = (float*)d_out;

    float *buf2, *a2, *reg, *clsraw;
    cudaGetSymbolAddress((void**)&buf2,   g_buf2);
    cudaGetSymbolAddress((void**)&a2,     g_a2);
    cudaGetSymbolAddress((void**)&reg,    g_reg);
    cudaGetSymbolAddress((void**)&clsraw, g_cls);
    float* feats = out + OFF_FEATS;

    cudaFuncSetAttribute(fused_k<true,  false, 2>, cudaFuncAttributeMaxDynamicSharedMemorySize, SMEM_BYTES);
    cudaFuncSetAttribute(fused_k<false, false, 4>, cudaFuncAttributeMaxDynamicSharedMemorySize, SMEM_BYTES);
    cudaFuncSetAttribute(fused_k<false, false, 0>, cudaFuncAttributeMaxDynamicSharedMemorySize, SMEM_BYTES);
    cudaFuncSetAttribute(fused_k<true,  true,  3>, cudaFuncAttributeMaxDynamicSharedMemorySize, SMEM_BYTES);
    cudaFuncSetAttribute(fused_k<true,  false, 5>, cudaFuncAttributeMaxDynamicSharedMemorySize, SMEM_BYTES);

    const int gy_N  = (NACT + 127) / 128;          // 782
    const int gy_NK = ((int)TOT_NK + 127) / 128;   // 4688

    KParams p;

    // 1. pred12 (two-layer, resid = actors from smem A)
    p = {}; p.A = actors; p.aStride = 0;
    p.B1 = pred_W1; p.b1Stride = (long)DD * DD; p.ldB1 = DD; p.ncols1 = DD;
    p.B2 = pred_W2; p.b2Stride = (long)DD * DD;
    p.M = NACT; p.g1 = pred_g1; p.bt1 = pred_b1; p.g2 = pred_g2; p.bt2 = pred_b2;
    p.Out = buf2;
    fused_k<true, false, 2><<<dim3(KM, gy_N), 512, SMEM_BYTES>>>(p);

    // 2. predo (single layer, MT=1 128x64 tile, bias + ctr, reg layout)
    p = {}; p.A = buf2; p.aStride = (long)NACT * DD;
    p.B1 = pred_Wo; p.b1Stride = (long)DD * OUT2P; p.ldB1 = OUT2P; p.ncols1 = OUT2P;
    p.M = NACT; p.Out = reg; p.biasN = pred_bo; p.ctrs = ctrs;
    fused_k<false, false, 4><<<dim3(KM, gy_N), 512, SMEM_BYTES>>>(p);

    // 3. a2 = actors @ agt_W[128:256]
    p = {}; p.A = actors; p.aStride = 0;
    p.B1 = agt_W + DD * DD; p.b1Stride = 0; p.ldB1 = DD; p.ncols1 = DD;
    p.M = NACT; p.Out = a2;
    fused_k<false, false, 0><<<dim3(1, gy_N), 512, SMEM_BYTES>>>(p);

    // 4. distagt (A generated; two-layer; pre-add a2; out -> feats)
    p = {}; p.A = nullptr; p.aStride = 0;
    p.B1 = dist_W1; p.b1Stride = 0; p.ldB1 = DD; p.ncols1 = DD;
    p.B2 = agt_W;  p.b2Stride = 0;
    p.M = (int)TOT_NK; p.g1 = dist_g1; p.bt1 = dist_b1; p.g2 = agt_g; p.bt2 = agt_b;
    p.Out = feats; p.pre = a2;
    p.ctrs = ctrs; p.dW0 = dist_W0; p.db0 = dist_b0; p.dReg = reg;
    fused_k<true, true, 3><<<dim3(1, gy_NK), 512, SMEM_BYTES>>>(p);

    // 5. cls12 (two-layer, resid = feats from smem A, fused Wo dot)
    p = {}; p.A = feats; p.aStride = 0;
    p.B1 = cls_W1; p.b1Stride = 0; p.ldB1 = DD; p.ncols1 = DD;
    p.B2 = cls_W2; p.b2Stride = 0;
    p.M = (int)TOT_NK; p.g1 = cls_g1; p.bt1 = cls_b1; p.g2 = cls_g2; p.bt2 = cls_b2;
    p.wo = cls_Wo; p.wob = cls_bo; p.clsOut = clsraw;
    fused_k<true, false, 5><<<dim3(1, gy_NK), 512, SMEM_BYTES>>>(p);

    // 6. softmax + stable sort + gather
    {
        long threads = (long)NACT * 32;
        final_k<<<(int)((threads + 255) / 256), 256>>>(clsraw, reg, out);
    }
}

// round 16
// speedup vs baseline: 1.2123x; 1.2120x over previous
#include <cuda_runtime.h>
#include <cstdint>

// ---------------------------------------------------------------------------
// PredNetNoMap — bf16x3 split mma.sync with ldmatrix operand fetch.
// 6 launches (same structure/epilogues as R6; only operand path changed):
//  1. pred12 : buf2 = relu(gn(relu(gn(actors@W1[k]))@W2[k]) + actors)
//  2. predo  : reg  = buf2@Wo[k] + bo[k] + ctr          (MT=1: 128x64 tile)
//  3. a2     : a2   = actors @ agt_W[128:256]
//  4. distagt: feats= relu(gn(relu(gn(AGEN@dist_W1))@agt_Wtop + a2))
//  5. cls12  : cls  = (relu(gn(relu(gn(feats@cW1))@cW2)+feats)) . Wo+bo
//  6. final  : softmax(K=6) + stable desc sort + gather
// ---------------------------------------------------------------------------

namespace {
constexpr int  NACT  = 100000;
constexpr int  KM    = 6;
constexpr int  DD    = 128;
constexpr int  OUT2P = 60;
constexpr long TOT_NK = (long)NACT * KM;
constexpr long OFF_REG   = TOT_NK;
constexpr long OFF_FEATS = OFF_REG + TOT_NK * OUT2P;

// bf16 tile leading dim: 136 elems = 272 B rows. Row step mod 128B = 16B ->
// 8 consecutive ldmatrix row-chunks hit all 32 banks exactly once.
constexpr int LDT = 136;
constexpr int TILE_B = 128 * LDT * 2;          // 34,816 B per tile
constexpr int SB_AH  = 0;
constexpr int SB_AL  = SB_AH + TILE_B;
constexpr int SB_BH  = SB_AL + TILE_B;
constexpr int SB_BL  = SB_BH + TILE_B;
constexpr int SB_VH  = SB_BL + TILE_B;
constexpr int SB_VL  = SB_VH + TILE_B;
constexpr int SB_RED  = SB_VL + TILE_B;        // float[128*17]
constexpr int SB_RED2 = SB_RED  + 128 * 17 * 4;
constexpr int SB_STAT = SB_RED2 + 128 * 17 * 4; // float[256]
constexpr int SMEM_BYTES = SB_STAT + 256 * 4;   // 227,328 B
}

// scratch (static device memory; no runtime allocation)
__device__ float g_buf2[TOT_NK * DD];
__device__ float g_a2[(long)NACT * DD];
__device__ float g_reg[TOT_NK * OUT2P];
__device__ float g_cls[TOT_NK];

struct KParams {
    const float* A;  long aStride;
    const float* B1; long b1Stride; int ldB1; int ncols1;
    const float* B2; long b2Stride;
    int M;
    const float* g1; const float* bt1;
    const float* g2; const float* bt2;
    float* Out;
    const float* pre;                       // EPIO3 pre-GN add (row nk/6)
    const float* biasN; const float* ctrs;  // EPIO4 / AGEN
    const float* wo; const float* wob; float* clsOut;      // EPIO5
    const float* dW0; const float* db0; const float* dReg; // AGEN
};

// ---------------- low-level helpers ----------------
__device__ __forceinline__ uint32_t pack_bf(float v_even, float v_odd) {
    uint32_t r;  // low16 = bf16(v_even), high16 = bf16(v_odd)
    asm("cvt.rn.bf16x2.f32 %0, %1, %2;" : "=r"(r) : "f"(v_odd), "f"(v_even));
    return r;
}
__device__ __forceinline__ float bf_lo_f(uint32_t p) { return __uint_as_float(p << 16); }
__device__ __forceinline__ float bf_hi_f(uint32_t p) { return __uint_as_float(p & 0xFFFF0000u); }
__device__ __forceinline__ uint2 split2(float v0, float v1) {
    uint32_t h = pack_bf(v0, v1);
    uint32_t l = pack_bf(v0 - bf_lo_f(h), v1 - bf_hi_f(h));
    return make_uint2(h, l);
}
__device__ __forceinline__ void mma16(float* d, const uint32_t* a, uint32_t b0, uint32_t b1) {
    asm volatile("mma.sync.aligned.m16n8k16.row.col.f32.bf16.bf16.f32 "
                 "{%0,%1,%2,%3},{%4,%5,%6,%7},{%8,%9},{%0,%1,%2,%3};"
                 : "+f"(d[0]), "+f"(d[1]), "+f"(d[2]), "+f"(d[3])
                 : "r"(a[0]), "r"(a[1]), "r"(a[2]), "r"(a[3]), "r"(b0), "r"(b1));
}
__device__ __forceinline__ void ldsm4(uint32_t* r, uint32_t addr) {
    asm volatile("ldmatrix.sync.aligned.m8n8.x4.shared.b16 {%0,%1,%2,%3}, [%4];"
                 : "=r"(r[0]), "=r"(r[1]), "=r"(r[2]), "=r"(r[3]) : "r"(addr));
}
__device__ __forceinline__ void ldsm4t(uint32_t* r, uint32_t addr) {
    asm volatile("ldmatrix.sync.aligned.m8n8.x4.trans.shared.b16 {%0,%1,%2,%3}, [%4];"
                 : "=r"(r[0]), "=r"(r[1]), "=r"(r[2]), "=r"(r[3]) : "r"(addr));
}

// global fp32 A [rows x 128] -> bf16 hi/lo tiles [row][k], ld = LDT
__device__ __forceinline__ void loadA(char* smc, const float* Agl,
                                      int rowBase, int M, int tid) {
#pragma unroll
    for (int t = 0; t < 8; t++) {
        int task = t * 512 + tid;          // 4096 float4 tasks
        int row = task >> 5;
        int k0  = (task & 31) * 4;
        float4 v = make_float4(0.f, 0.f, 0.f, 0.f);
        if (rowBase + row < M)
            v = *reinterpret_cast<const float4*>(Agl + (long)(rowBase + row) * DD + k0);
        uint2 p0 = split2(v.x, v.y);
        uint2 p1 = split2(v.z, v.w);
        int off = (row * LDT + k0) * 2;    // k0 mult of 4 -> 8B aligned
        *reinterpret_cast<uint2*>(smc + SB_AH + off) = make_uint2(p0.x, p1.x);
        *reinterpret_cast<uint2*>(smc + SB_AL + off) = make_uint2(p0.y, p1.y);
    }
}

// global fp32 B [128 x ncols] (ld=ldB) -> bf16 hi/lo tiles [k][n], ld = LDT
__device__ __forceinline__ void loadB(char* smc, const float* Bgl,
                                      int ldB, int ncols, int tid) {
#pragma unroll
    for (int t = 0; t < 8; t++) {
        int task = t * 512 + tid;          // 4096 tasks: 128 k x 32 n4
        int k  = task >> 5;
        int n0 = (task & 31) * 4;
        float4 v = make_float4(0.f, 0.f, 0.f, 0.f);
        if (n0 + 4 <= ncols)
            v = *reinterpret_cast<const float4*>(Bgl + (long)k * ldB + n0);
        uint2 p0 = split2(v.x, v.y);
        uint2 p1 = split2(v.z, v.w);
        int off = (k * LDT + n0) * 2;
        *reinterpret_cast<uint2*>(smc + SB_BH + off) = make_uint2(p0.x, p1.x);
        *reinterpret_cast<uint2*>(smc + SB_BL + off) = make_uint2(p0.y, p1.y);
    }
}

// 128x(64|128)x128 layer, bf16x3 split via ldmatrix fragments
// MT=2: warp tile 32r x 32c (mw 0..3, nw 0..3). MT=1: 16r x 32c (mw 0..7, nw 0..1).
template<int MT>
__device__ __forceinline__ void compute_layer(float acc[MT][4][4], char* smc,
        int aOff, int bOff, int mw, int nw, int lane) {
    const uint32_t sb = (uint32_t)__cvta_generic_to_shared(smc);
    const int lm = lane & 15, lh = lane >> 4;        // A: row lm, k-half lh
    const int j  = lane >> 3, i  = lane & 7;         // B: tile j, row i
    const int rowA = (MT == 2 ? mw * 32 : mw * 16) + lm;
    const uint32_t aH0 = sb + aOff + (rowA * LDT + lh * 8) * 2;
    const uint32_t aL0 = aH0 + (uint32_t)TILE_B;
    const int bRow = (j & 1) * 8 + i;
    const int bCol = nw * 32 + (j >> 1) * 8;
    const uint32_t bH0 = sb + bOff + (bRow * LDT + bCol) * 2;
    const uint32_t bL0 = bH0 + (uint32_t)TILE_B;
#pragma unroll
    for (int kc = 0; kc < 8; kc++) {
        uint32_t ah[MT][4], al[MT][4];
        ldsm4(ah[0], aH0 + kc * 32);
        ldsm4(al[0], aL0 + kc * 32);
        if (MT == 2) {
            ldsm4(ah[1], aH0 + 16 * LDT * 2 + kc * 32);
            ldsm4(al[1], aL0 + 16 * LDT * 2 + kc * 32);
        }
        uint32_t bh[8], bl[8];                       // [n8grp*2 + {b0,b1}]
        ldsm4t(bh + 0, bH0 + kc * (16 * LDT * 2));
        ldsm4t(bh + 4, bH0 + 32 + kc * (16 * LDT * 2));
        ldsm4t(bl + 0, bL0 + kc * (16 * LDT * 2));
        ldsm4t(bl + 4, bL0 + 32 + kc * (16 * LDT * 2));
#pragma unroll
        for (int nt = 0; nt < 4; nt++) {
            uint32_t b0 = bh[nt * 2], b1 = bh[nt * 2 + 1];
            uint32_t c0 = bl[nt * 2], c1 = bl[nt * 2 + 1];
#pragma unroll
            for (int mt = 0; mt < MT; mt++) {
                mma16(acc[mt][nt], ah[mt], b0, b1);
                mma16(acc[mt][nt], al[mt], b0, b1);
                mma16(acc[mt][nt], ah[mt], c0, c1);
            }
        }
    }
}

// GN row statistics (MT=2 path): mean/rstd over the 128-col row
__device__ __forceinline__ void gn_stats2(float acc[2][4][4], char* smc,
                                          int mw, int nw, int gid, int tig, int tid) {
    float* red  = (float*)(smc + SB_RED);
    float* red2 = (float*)(smc + SB_RED2);
    float* rstat= (float*)(smc + SB_STAT);
#pragma unroll
    for (int mt = 0; mt < 2; mt++)
#pragma unroll
        for (int h = 0; h < 2; h++) {
            int r = mw * 32 + mt * 16 + h * 8 + gid;
            float s = 0.f, q = 0.f;
#pragma unroll
            for (int nt = 0; nt < 4; nt++) {
                float v0 = acc[mt][nt][h * 2], v1 = acc[mt][nt][h * 2 + 1];
                s += v0 + v1;
                q += fmaf(v0, v0, v1 * v1);
            }
            red [r * 17 + nw * 4 + tig] = s;
            red2[r * 17 + nw * 4 + tig] = q;
        }
    __syncthreads();
    if (tid < 128) {
        float s = 0.f, q = 0.f;
#pragma unroll
        for (int g = 0; g < 16; g++) { s += red[tid * 17 + g]; q += red2[tid * 17 + g]; }
        float m   = s * (1.f / DD);
        float var = q * (1.f / DD) - m * m;
        rstat[tid]       = m;
        rstat[128 + tid] = rsqrtf(var + 1e-5f);
    }
    __syncthreads();
}

// EPIO: 0 plain store | 2 GN+resid(A)+relu | 3 preadd+GN+relu
//       4 bias+ctr -> reg layout (MT=1, 64 cols) | 5 GN+resid(A)+relu+dot(wo)
template<bool TWOLAYER, bool AGEN, int EPIO>
__global__ __launch_bounds__(512, 1)
void fused_k(KParams p) {
    constexpr int MT = (EPIO == 4) ? 1 : 2;
    extern __shared__ char smc[];
    float* rstat = (float*)(smc + SB_STAT);

    const int tid  = threadIdx.x;
    const int lane = tid & 31;
    const int w    = tid >> 5;
    const int gid  = lane >> 2, tig = lane & 3;
    const int mw   = (MT == 2) ? (w >> 2) : (w >> 1);
    const int nw   = (MT == 2) ? (w & 3)  : (w & 1);
    const int z    = blockIdx.x;
    const int rowBase = blockIdx.y * 128;

    float acc[MT][4][4];
#pragma unroll
    for (int mt = 0; mt < MT; mt++)
#pragma unroll
        for (int nt = 0; nt < 4; nt++)
#pragma unroll
            for (int jj = 0; jj < 4; jj++) acc[mt][nt][jj] = 0.f;

    // ---------------- stage A + B1 ----------------
    if (AGEN) {
        if (tid < 128) {
            int nk = rowBase + tid;
            float dx = 0.f, dy = 0.f;
            if (nk < p.M) {
                long n = nk / KM;
                dx = p.ctrs[n * 2 + 0] - p.dReg[(long)nk * OUT2P + 58];
                dy = p.ctrs[n * 2 + 1] - p.dReg[(long)nk * OUT2P + 59];
            }
            rstat[tid] = dx; rstat[128 + tid] = dy;
        }
        __syncthreads();
#pragma unroll
        for (int t = 0; t < 16; t++) {
            int pair = t * 512 + tid;      // 8192 bf16-pairs
            int r = pair >> 6;
            int k = (pair & 63) * 2;
            float dx = rstat[r], dy = rstat[128 + r];
            float v0 = fmaxf(fmaf(dx, __ldg(p.dW0 + k),     fmaf(dy, __ldg(p.dW0 + DD + k),     __ldg(p.db0 + k))),     0.f);
            float v1 = fmaxf(fmaf(dx, __ldg(p.dW0 + k + 1), fmaf(dy, __ldg(p.dW0 + DD + k + 1), __ldg(p.db0 + k + 1))), 0.f);
            uint2 hl = split2(v0, v1);
            int off = (r * LDT + k) * 2;
            *(uint32_t*)(smc + SB_AH + off) = hl.x;
            *(uint32_t*)(smc + SB_AL + off) = hl.y;
        }
    } else {
        loadA(smc, p.A + (long)z * p.aStride, rowBase, p.M, tid);
    }
    loadB(smc, p.B1 + (long)z * p.b1Stride, p.ldB1, p.ncols1, tid);
    __syncthreads();

    // ---------------- layer 1 ----------------
    compute_layer<MT>(acc, smc, SB_AH, SB_BH, mw, nw, lane);

    if (TWOLAYER) {
        gn_stats2(acc, smc, mw, nw, gid, tig, tid);
        // B1 dead after gn_stats2's syncs -> stream in B2 (overlaps GN math)
        loadB(smc, p.B2 + (long)z * p.b2Stride, DD, DD, tid);
        const float* gg = p.g1  + (long)z * DD;
        const float* bb = p.bt1 + (long)z * DD;
#pragma unroll
        for (int mt = 0; mt < 2; mt++)
#pragma unroll
            for (int h = 0; h < 2; h++) {
                int r = mw * 32 + mt * 16 + h * 8 + gid;
                float m = rstat[r], rs = rstat[128 + r];
#pragma unroll
                for (int nt = 0; nt < 4; nt++) {
                    int col = nw * 32 + nt * 8 + tig * 2;
                    float v0 = fmaxf((acc[mt][nt][h * 2]     - m) * rs * __ldg(gg + col)     + __ldg(bb + col),     0.f);
                    float v1 = fmaxf((acc[mt][nt][h * 2 + 1] - m) * rs * __ldg(gg + col + 1) + __ldg(bb + col + 1), 0.f);
                    uint2 hl = split2(v0, v1);
                    int off = (r * LDT + col) * 2;
                    *(uint32_t*)(smc + SB_VH + off) = hl.x;
                    *(uint32_t*)(smc + SB_VL + off) = hl.y;
                    acc[mt][nt][h * 2] = 0.f; acc[mt][nt][h * 2 + 1] = 0.f;
                }
            }
        __syncthreads();
        // ---------------- layer 2 ----------------
        compute_layer<MT>(acc, smc, SB_VH, SB_BH, mw, nw, lane);
    }

    // ---------------- out epilogue ----------------
    if (EPIO == 0) {
#pragma unroll
        for (int mt = 0; mt < 2; mt++)
#pragma unroll
            for (int h = 0; h < 2; h++) {
                int r = mw * 32 + mt * 16 + h * 8 + gid;
                int n = rowBase + r;
                if (n < p.M) {
#pragma unroll
                    for (int nt = 0; nt < 4; nt++) {
                        int col = nw * 32 + nt * 8 + tig * 2;
                        *reinterpret_cast<float2*>(p.Out + ((long)z * p.M + n) * DD + col) =
                            make_float2(acc[mt][nt][h * 2], acc[mt][nt][h * 2 + 1]);
                    }
                }
            }
        return;
    }
    if (EPIO == 4) {   // MT=1: rows mw*16.., cols nw*32.. (64 wide, ncols=60)
#pragma unroll
        for (int h = 0; h < 2; h++) {
            int r = mw * 16 + h * 8 + gid;
            int n = rowBase + r;
            if (n < p.M) {
                float2 cc = *reinterpret_cast<const float2*>(p.ctrs + (long)n * 2);
#pragma unroll
                for (int nt = 0; nt < 4; nt++) {
                    int col = nw * 32 + nt * 8 + tig * 2;
                    if (col < OUT2P) {
                        float v0 = acc[0][nt][h * 2]     + __ldg(p.biasN + z * OUT2P + col)     + cc.x;
                        float v1 = acc[0][nt][h * 2 + 1] + __ldg(p.biasN + z * OUT2P + col + 1) + cc.y;
                        *reinterpret_cast<float2*>(p.Out + ((long)n * KM + z) * OUT2P + col) =
                            make_float2(v0, v1);
                    }
                }
            }
        }
        return;
    }

    if (EPIO == 3) {   // pre-GN add of a2[n/6]
#pragma unroll
        for (int mt = 0; mt < 2; mt++)
#pragma unroll
            for (int h = 0; h < 2; h++) {
                int r = mw * 32 + mt * 16 + h * 8 + gid;
                int n = rowBase + r;
                if (n < p.M) {
                    const float* pa = p.pre + (long)(n / KM) * DD;
#pragma unroll
                    for (int nt = 0; nt < 4; nt++) {
                        int col = nw * 32 + nt * 8 + tig * 2;
                        float2 pv = *reinterpret_cast<const float2*>(pa + col);
                        acc[mt][nt][h * 2]     += pv.x;
                        acc[mt][nt][h * 2 + 1] += pv.y;
                    }
                }
            }
    }
    gn_stats2(acc, smc, mw, nw, gid, tig, tid);
    {
        float* red = (float*)(smc + SB_RED);
        const float* gg = p.g2  + (long)z * DD;
        const float* bb = p.bt2 + (long)z * DD;
#pragma unroll
        for (int mt = 0; mt < 2; mt++)
#pragma unroll
            for (int h = 0; h < 2; h++) {
                int r = mw * 32 + mt * 16 + h * 8 + gid;
                int n = rowBase + r;
                float m = rstat[r], rs = rstat[128 + r];
                float ds = 0.f;
#pragma unroll
                for (int nt = 0; nt < 4; nt++) {
                    int col = nw * 32 + nt * 8 + tig * 2;
                    float v0 = (acc[mt][nt][h * 2]     - m) * rs * __ldg(gg + col)     + __ldg(bb + col);
                    float v1 = (acc[mt][nt][h * 2 + 1] - m) * rs * __ldg(gg + col + 1) + __ldg(bb + col + 1);
                    if (EPIO == 2 || EPIO == 5) {   // residual = original A tile (hi+lo)
                        int off = (r * LDT + col) * 2;
                        uint32_t hp = *(const uint32_t*)(smc + SB_AH + off);
                        uint32_t lp = *(const uint32_t*)(smc + SB_AL + off);
                        v0 += bf_lo_f(hp) + bf_lo_f(lp);
                        v1 += bf_hi_f(hp) + bf_hi_f(lp);
                    }
                    v0 = fmaxf(v0, 0.f); v1 = fmaxf(v1, 0.f);
                    if (EPIO == 5) {
                        ds += v0 * __ldg(p.wo + col) + v1 * __ldg(p.wo + col + 1);
                    } else if (n < p.M) {
                        *reinterpret_cast<float2*>(p.Out + ((long)z * p.M + n) * DD + col) =
                            make_float2(v0, v1);
                    }
                }
                if (EPIO == 5) red[r * 17 + nw * 4 + tig] = ds;
            }
    }
    if (EPIO == 5) {
        __syncthreads();
        float* red = (float*)(smc + SB_RED);
        if (tid < 128) {
            float s = 0.f;
#pragma unroll
            for (int g = 0; g < 16; g++) s += red[tid * 17 + g];
            int n = rowBase + tid;
            if (n < p.M) p.clsOut[n] = s + __ldg(p.wob);
        }
    }
}

// softmax over K=6, stable descending sort, reorder cls + reg into d_out
__global__ void final_k(const float* __restrict__ clsRaw, const float* __restrict__ reg,
                        float* __restrict__ out) {
    long gw = ((long)blockIdx.x * blockDim.x + threadIdx.x) >> 5;
    int lane = threadIdx.x & 31;
    if (gw >= NACT) return;
    long n = gw;
    float v[KM];
#pragma unroll
    for (int k = 0; k < KM; k++) v[k] = clsRaw[n * KM + k];
    float mx = v[0];
#pragma unroll
    for (int k = 1; k < KM; k++) mx = fmaxf(mx, v[k]);
    float e[KM]; float s = 0.f;
#pragma unroll
    for (int k = 0; k < KM; k++) { e[k] = expf(v[k] - mx); s += e[k]; }
    float inv = 1.f / s;
    int order[KM]; bool used[KM];
#pragma unroll
    for (int k = 0; k < KM; k++) used[k] = false;
#pragma unroll
    for (int j = 0; j < KM; j++) {   // stable selection: strict >, first index wins
        int best = 0; float bv = -1e30f;
#pragma unroll
        for (int k = 0; k < KM; k++)
            if (!used[k] && v[k] > bv) { bv = v[k]; best = k; }
        used[best] = true;
        order[j] = best;
    }
    if (lane < KM) out[n * KM + lane] = e[order[lane]] * inv;
    const float* src0 = reg + n * KM * OUT2P;
    float* dst0 = out + OFF_REG + n * KM * OUT2P;
#pragma unroll
    for (int j = 0; j < KM; j++) {
        const float* src = src0 + order[j] * OUT2P;
        float* dst = dst0 + (long)j * OUT2P;
        for (int t = lane; t < OUT2P; t += 32) dst[t] = src[t];
    }
}

extern "C" void kernel_launch(void* const* d_in, const int* in_sizes, int n_in,
                              void* d_out, int out_size) {
    const float* actors  = (const float*)d_in[0];
    const float* ctrs    = (const float*)d_in[1];
    const float* pred_W1 = (const float*)d_in[2];
    const float* pred_g1 = (const float*)d_in[3];
    const float* pred_b1 = (const float*)d_in[4];
    const float* pred_W2 = (const float*)d_in[5];
    const float* pred_g2 = (const float*)d_in[6];
    const float* pred_b2 = (const float*)d_in[7];
    const float* pred_Wo = (const float*)d_in[8];
    const float* pred_bo = (const float*)d_in[9];
    const float* dist_W0 = (const float*)d_in[10];
    const float* dist_b0 = (const float*)d_in[11];
    const float* dist_W1 = (const float*)d_in[12];
    const float* dist_g1 = (const float*)d_in[13];
    const float* dist_b1 = (const float*)d_in[14];
    const float* agt_W   = (const float*)d_in[15];
    const float* agt_g   = (const float*)d_in[16];
    const float* agt_b   = (const float*)d_in[17];
    const float* cls_W1  = (const float*)d_in[18];
    const float* cls_g1  = (const float*)d_in[19];
    const float* cls_b1  = (const float*)d_in[20];
    const float* cls_W2  = (const float*)d_in[21];
    const float* cls_g2  = (const float*)d_in[22];
    const float* cls_b2  = (const float*)d_in[23];
    const float* cls_Wo  = (const float*)d_in[24];
    const float* cls_bo  = (const float*)d_in[25];
    float* out = (float*)d_out;

    float *buf2, *a2, *reg, *clsraw;
    cudaGetSymbolAddress((void**)&buf2,   g_buf2);
    cudaGetSymbolAddress((void**)&a2,     g_a2);
    cudaGetSymbolAddress((void**)&reg,    g_reg);
    cudaGetSymbolAddress((void**)&clsraw, g_cls);
    float* feats = out + OFF_FEATS;

    cudaFuncSetAttribute(fused_k<true,  false, 2>, cudaFuncAttributeMaxDynamicSharedMemorySize, SMEM_BYTES);
    cudaFuncSetAttribute(fused_k<false, false, 4>, cudaFuncAttributeMaxDynamicSharedMemorySize, SMEM_BYTES);
    cudaFuncSetAttribute(fused_k<false, false, 0>, cudaFuncAttributeMaxDynamicSharedMemorySize, SMEM_BYTES);
    cudaFuncSetAttribute(fused_k<true,  true,  3>, cudaFuncAttributeMaxDynamicSharedMemorySize, SMEM_BYTES);
    cudaFuncSetAttribute(fused_k<true,  false, 5>, cudaFuncAttributeMaxDynamicSharedMemorySize, SMEM_BYTES);

    const int gy_N  = (NACT + 127) / 128;          // 782
    const int gy_NK = ((int)TOT_NK + 127) / 128;   // 4688

    KParams p;

    // 1. pred12 (two-layer, resid = actors from smem A)
    p = {}; p.A = actors; p.aStride = 0;
    p.B1 = pred_W1; p.b1Stride = (long)DD * DD; p.ldB1 = DD; p.ncols1 = DD;
    p.B2 = pred_W2; p.b2Stride = (long)DD * DD;
    p.M = NACT; p.g1 = pred_g1; p.bt1 = pred_b1; p.g2 = pred_g2; p.bt2 = pred_b2;
    p.Out = buf2;
    fused_k<true, false, 2><<<dim3(KM, gy_N), 512, SMEM_BYTES>>>(p);

    // 2. predo (single layer, MT=1 128x64 tile, bias + ctr, reg layout)
    p = {}; p.A = buf2; p.aStride = (long)NACT * DD;
    p.B1 = pred_Wo; p.b1Stride = (long)DD * OUT2P; p.ldB1 = OUT2P; p.ncols1 = OUT2P;
    p.M = NACT; p.Out = reg; p.biasN = pred_bo; p.ctrs = ctrs;
    fused_k<false, false, 4><<<dim3(KM, gy_N), 512, SMEM_BYTES>>>(p);

    // 3. a2 = actors @ agt_W[128:256]
    p = {}; p.A = actors; p.aStride = 0;
    p.B1 = agt_W + DD * DD; p.b1Stride = 0; p.ldB1 = DD; p.ncols1 = DD;
    p.M = NACT; p.Out = a2;
    fused_k<false, false, 0><<<dim3(1, gy_N), 512, SMEM_BYTES>>>(p);

    // 4. distagt (A generated; two-layer; pre-add a2; out -> feats)
    p = {}; p.A = nullptr; p.aStride = 0;
    p.B1 = dist_W1; p.b1Stride = 0; p.ldB1 = DD; p.ncols1 = DD;
    p.B2 = agt_W;  p.b2Stride = 0;
    p.M = (int)TOT_NK; p.g1 = dist_g1; p.bt1 = dist_b1; p.g2 = agt_g; p.bt2 = agt_b;
    p.Out = feats; p.pre = a2;
    p.ctrs = ctrs; p.dW0 = dist_W0; p.db0 = dist_b0; p.dReg = reg;
    fused_k<true, true, 3><<<dim3(1, gy_NK), 512, SMEM_BYTES>>>(p);

    // 5. cls12 (two-layer, resid = feats from smem A, fused Wo dot)
    p = {}; p.A = feats; p.aStride = 0;
    p.B1 = cls_W1; p.b1Stride = 0; p.ldB1 = DD; p.ncols1 = DD;
    p.B2 = cls_W2; p.b2Stride = 0;
    p.M = (int)TOT_NK; p.g1 = cls_g1; p.bt1 = cls_b1; p.g2 = cls_g2; p.bt2 = cls_b2;
    p.wo = cls_Wo; p.wob = cls_bo; p.clsOut = clsraw;
    fused_k<true, false, 5><<<dim3(1, gy_NK), 512, SMEM_BYTES>>>(p);

    // 6. softmax + stable sort + gather
    {
        long threads = (long)NACT * 32;
        final_k<<<(int)((threads + 255) / 256), 256>>>(clsraw, reg, out);
    }
}